// round 16
// baseline (speedup 1.0000x reference)
#include <cuda_runtime.h>

// HOAF: per-group (G=32, cpg=8) polynomial expansion (164 features) +
// per-group 8x164 matvec. B=16, C=256, HW=3136.
//
// R10: identical design to R9 (closed-form constexpr feature indices, static
// ping-pong distance-1 weight prefetch, macro body, R2 champion shape), with
// the preprocessor bug fixed: buffer members are named buf##_N (underscore
// separator) so token pasting never collides with the pp-number "3.x".
// R9 rationale: R7/R8's 164-step chain stopped fully unrolling (mutable fc
// counter) -> dynamic smem addressing (alu 17.7%, fma 46%). All indices are
// now fold-time constants. Predicted: alu ~6%, fma ~70%, ~85us.

typedef unsigned long long u64;

#define HW   3136
#define TPB  224

__device__ __forceinline__ u64 fma2(u64 a, u64 b, u64 c) {
    u64 d;
    asm("fma.rn.f32x2 %0, %1, %2, %3;" : "=l"(d) : "l"(a), "l"(b), "l"(c));
    return d;
}
__device__ __forceinline__ u64 mul2(u64 a, u64 b) {
    u64 d;
    asm("mul.rn.f32x2 %0, %1, %2;" : "=l"(d) : "l"(a), "l"(b));
    return d;
}

// ---- closed-form traversal indices (pure arithmetic; folds to literals) ----
// Traversal: t=0..7 deg1; then per pair (i,j), i<=j: pair feature, then its
// triples (i,j,k), k=j..7.
// P[i] = triples contributed by full rows a<i = prefix of (8-a)(9-a)/2.
__device__ __forceinline__ constexpr int fcPair(int i, int j) {
    constexpr int P[8] = {0, 36, 64, 85, 100, 110, 116, 119};
    const int p2  = 8 * i - (i * (i - 1)) / 2 + (j - i);
    const int p3b = P[i] + ((8 - i) * (9 - i) - (8 - j) * (9 - j)) / 2;
    return 8 + p2 + p3b;
}
__device__ __forceinline__ constexpr int fcTrip(int i, int j, int k) {
    return fcPair(i, j) + 1 + (k - j);
}

// ---- ping-pong weight pipeline (static: fc is a fold-time constant) ----
#define PREF(buf, f) do {                                                   \
    const ulonglong2* _wp = (const ulonglong2*)(wdup + (f) * 8);            \
    buf##_0 = _wp[0]; buf##_1 = _wp[1]; buf##_2 = _wp[2]; buf##_3 = _wp[3]; \
} while (0)

#define FMAS(buf, fA, fB) do {                                              \
    accA[0] = fma2(fA, buf##_0.x, accA[0]);                                 \
    accB[0] = fma2(fB, buf##_0.x, accB[0]);                                 \
    accA[1] = fma2(fA, buf##_0.y, accA[1]);                                 \
    accB[1] = fma2(fB, buf##_0.y, accB[1]);                                 \
    accA[2] = fma2(fA, buf##_1.x, accA[2]);                                 \
    accB[2] = fma2(fB, buf##_1.x, accB[2]);                                 \
    accA[3] = fma2(fA, buf##_1.y, accA[3]);                                 \
    accB[3] = fma2(fB, buf##_1.y, accB[3]);                                 \
    accA[4] = fma2(fA, buf##_2.x, accA[4]);                                 \
    accB[4] = fma2(fB, buf##_2.x, accB[4]);                                 \
    accA[5] = fma2(fA, buf##_2.y, accA[5]);                                 \
    accB[5] = fma2(fB, buf##_2.y, accB[5]);                                 \
    accA[6] = fma2(fA, buf##_3.x, accA[6]);                                 \
    accB[6] = fma2(fB, buf##_3.x, accB[6]);                                 \
    accA[7] = fma2(fA, buf##_3.y, accA[7]);                                 \
    accB[7] = fma2(fB, buf##_3.y, accB[7]);                                 \
} while (0)

// Prefetch feature fc+1 (clamped; last step redundantly reloads 163) into
// the opposite buffer, then FMA feature fc from the current buffer.
#define STEP(fcv, fA, fB) do {                                              \
    const int _f = (fcv);                                                   \
    const int _n = (_f + 1 < 164) ? _f + 1 : 163;                           \
    if ((_f & 1) == 0) { PREF(wO, _n); FMAS(wE, fA, fB); }                  \
    else               { PREF(wE, _n); FMAS(wO, fA, fB); }                  \
} while (0)

__global__ __launch_bounds__(TPB, 2) void hoaf_kernel(
    const float* __restrict__ x,
    const float* __restrict__ w1, const float* __restrict__ b1,
    const float* __restrict__ w2, const float* __restrict__ b2,
    const float* __restrict__ w3, const float* __restrict__ b3,
    float* __restrict__ out)
{
    // Weights in traversal order, 8 outputs per feature, each (w,w)-packed.
    __shared__ alignas(16) u64 wdup[1312];
    __shared__ u64 biasdup[8];

    const int tid = threadIdx.x;
    const int g = blockIdx.y;

    // Stage weights: traversal index t -> reference tensor element
    // (verified correct in R7/R8: rel_err 2.3e-7).
    for (int idx = tid; idx < 1312; idx += TPB) {
        const int t = idx >> 3;
        const int o = idx & 7;
        float v;
        if (t < 8) {
            v = w1[(g * 8 + o) * 8 + t];
        } else {
            int tt = t - 8;
            int p2 = 0, p3 = 0, rem = 0;
            bool found = false;
            for (int i = 0; i < 8 && !found; i++) {
                for (int j = i; j < 8; j++) {
                    const int blk = 1 + (8 - j);
                    if (tt < blk) { rem = tt; found = true; break; }
                    tt -= blk; p2++; p3 += 8 - j;
                }
            }
            if (rem == 0)
                v = w2[(g * 8 + o) * 36 + p2];
            else
                v = w3[(g * 8 + o) * 120 + p3 + (rem - 1)];
        }
        const unsigned int u = __float_as_uint(v);
        wdup[idx] = ((u64)u << 32) | u;
    }
    if (tid < 8) {
        const float v = b1[g * 8 + tid] + b2[g * 8 + tid] + b3[g * 8 + tid];
        const unsigned int u = __float_as_uint(v);
        biasdup[tid] = ((u64)u << 32) | u;
    }
    __syncthreads();

    // Pixel pair p in batches z and z+8.
    const int p = (blockIdx.x * TPB + tid) * 2;
    const size_t gbase = ((size_t)blockIdx.z * 256 + (size_t)g * 8) * HW + p;
    const size_t bstr  = (size_t)8 * 256 * HW;

    u64 XA[8], XB[8], accA[8], accB[8];
#pragma unroll
    for (int k = 0; k < 8; k++) {
        XA[k] = *(const u64*)(x + gbase + (size_t)k * HW);
        XB[k] = *(const u64*)(x + gbase + bstr + (size_t)k * HW);
    }
#pragma unroll
    for (int o = 0; o < 8; o++) { accA[o] = biasdup[o]; accB[o] = accA[o]; }

    ulonglong2 wE_0, wE_1, wE_2, wE_3;   // even-parity features
    ulonglong2 wO_0, wO_1, wO_2, wO_3;   // odd-parity features
    PREF(wE, 0);

    // Degree 1: traversal t = k.
#pragma unroll
    for (int k = 0; k < 8; k++)
        STEP(k, XA[k], XB[k]);

    // Pairs + triples; indices are closed-form in (i,j,k).
#pragma unroll
    for (int i = 0; i < 8; i++) {
#pragma unroll
        for (int j = i; j < 8; j++) {
            const u64 pA = mul2(XA[i], XA[j]);
            const u64 pB = mul2(XB[i], XB[j]);
            STEP(fcPair(i, j), pA, pB);
#pragma unroll
            for (int k = j; k < 8; k++)
                STEP(fcTrip(i, j, k), mul2(pA, XA[k]), mul2(pB, XB[k]));
        }
    }

#pragma unroll
    for (int o = 0; o < 8; o++) {
        *(u64*)(out + gbase + (size_t)o * HW) = accA[o];
        *(u64*)(out + gbase + bstr + (size_t)o * HW) = accB[o];
    }
}

extern "C" void kernel_launch(void* const* d_in, const int* in_sizes, int n_in,
                              void* d_out, int out_size)
{
    const float* x  = (const float*)d_in[0];
    const float* w1 = (const float*)d_in[1];
    const float* b1 = (const float*)d_in[2];
    const float* w2 = (const float*)d_in[3];
    const float* b2 = (const float*)d_in[4];
    const float* w3 = (const float*)d_in[5];
    const float* b3 = (const float*)d_in[6];

    dim3 grid(7, 32, 8);    // pixel-pair chunks, groups, batch pairs
    dim3 block(TPB);
    hoaf_kernel<<<grid, block>>>(x, w1, b1, w2, b2, w3, b3, (float*)d_out);
}

// round 17
// speedup vs baseline: 1.1898x; 1.1898x over previous
#include <cuda_runtime.h>

// HOAF: per-group (G=32, cpg=8) polynomial expansion (164 features) +
// per-group 8x164 matvec. B=16, C=256, HW=3136.
//
// R11: R7/R8/R10 all profiled identically (alu 17.7%, fma 46.5%) -- the +18us
// vs R2 was NOT the main loop: fma-seconds are constant (59us) across all
// rounds. The regression is the traversal-order STAGING loop (O(36) search
// run ~6x per thread = ~36% instruction overhead). Fix: stage per-FEATURE
// (164 threads, one search each, then 8 weight loads) -> staging cost /6.
// Main loop kept verbatim from R10 (static ping-pong distance-1 weight
// prefetch, closed-form constexpr indices, R2 champion shape: 2 pixel-units
// (batches z,z+8) x 8 outputs, TPB 224, bounds(224,2)).
// Predicted: alu ~6%; if prefetch hides LDS latency fma ~70% -> ~85-95us,
// else ~109us (ties champion; pivot to tensor cores next).

typedef unsigned long long u64;

#define HW   3136
#define TPB  224

__device__ __forceinline__ u64 fma2(u64 a, u64 b, u64 c) {
    u64 d;
    asm("fma.rn.f32x2 %0, %1, %2, %3;" : "=l"(d) : "l"(a), "l"(b), "l"(c));
    return d;
}
__device__ __forceinline__ u64 mul2(u64 a, u64 b) {
    u64 d;
    asm("mul.rn.f32x2 %0, %1, %2;" : "=l"(d) : "l"(a), "l"(b));
    return d;
}

// ---- closed-form traversal indices (pure arithmetic; folds to literals) ----
// Traversal: t=0..7 deg1; then per pair (i,j), i<=j: pair feature, then its
// triples (i,j,k), k=j..7.
// P[i] = triples contributed by full rows a<i = prefix of (8-a)(9-a)/2.
__device__ __forceinline__ constexpr int fcPair(int i, int j) {
    constexpr int P[8] = {0, 36, 64, 85, 100, 110, 116, 119};
    const int p2  = 8 * i - (i * (i - 1)) / 2 + (j - i);
    const int p3b = P[i] + ((8 - i) * (9 - i) - (8 - j) * (9 - j)) / 2;
    return 8 + p2 + p3b;
}
__device__ __forceinline__ constexpr int fcTrip(int i, int j, int k) {
    return fcPair(i, j) + 1 + (k - j);
}

// ---- ping-pong weight pipeline (static: fc is a fold-time constant) ----
#define PREF(buf, f) do {                                                   \
    const ulonglong2* _wp = (const ulonglong2*)(wdup + (f) * 8);            \
    buf##_0 = _wp[0]; buf##_1 = _wp[1]; buf##_2 = _wp[2]; buf##_3 = _wp[3]; \
} while (0)

#define FMAS(buf, fA, fB) do {                                              \
    accA[0] = fma2(fA, buf##_0.x, accA[0]);                                 \
    accB[0] = fma2(fB, buf##_0.x, accB[0]);                                 \
    accA[1] = fma2(fA, buf##_0.y, accA[1]);                                 \
    accB[1] = fma2(fB, buf##_0.y, accB[1]);                                 \
    accA[2] = fma2(fA, buf##_1.x, accA[2]);                                 \
    accB[2] = fma2(fB, buf##_1.x, accB[2]);                                 \
    accA[3] = fma2(fA, buf##_1.y, accA[3]);                                 \
    accB[3] = fma2(fB, buf##_1.y, accB[3]);                                 \
    accA[4] = fma2(fA, buf##_2.x, accA[4]);                                 \
    accB[4] = fma2(fB, buf##_2.x, accB[4]);                                 \
    accA[5] = fma2(fA, buf##_2.y, accA[5]);                                 \
    accB[5] = fma2(fB, buf##_2.y, accB[5]);                                 \
    accA[6] = fma2(fA, buf##_3.x, accA[6]);                                 \
    accB[6] = fma2(fB, buf##_3.x, accB[6]);                                 \
    accA[7] = fma2(fA, buf##_3.y, accA[7]);                                 \
    accB[7] = fma2(fB, buf##_3.y, accB[7]);                                 \
} while (0)

// Prefetch feature fc+1 (clamped; last step redundantly reloads 163) into
// the opposite buffer, then FMA feature fc from the current buffer.
#define STEP(fcv, fA, fB) do {                                              \
    const int _f = (fcv);                                                   \
    const int _n = (_f + 1 < 164) ? _f + 1 : 163;                           \
    if ((_f & 1) == 0) { PREF(wO, _n); FMAS(wE, fA, fB); }                  \
    else               { PREF(wE, _n); FMAS(wO, fA, fB); }                  \
} while (0)

__global__ __launch_bounds__(TPB, 2) void hoaf_kernel(
    const float* __restrict__ x,
    const float* __restrict__ w1, const float* __restrict__ b1,
    const float* __restrict__ w2, const float* __restrict__ b2,
    const float* __restrict__ w3, const float* __restrict__ b3,
    float* __restrict__ out)
{
    // Weights in traversal order, 8 outputs per feature, each (w,w)-packed.
    __shared__ alignas(16) u64 wdup[1312];
    __shared__ u64 biasdup[8];

    const int tid = threadIdx.x;
    const int g = blockIdx.y;

    // Stage weights per FEATURE: thread t<164 resolves traversal index t to
    // the reference tensor element once (search math verbatim from the
    // verified R7/R8/R10 staging), then loads/stores all 8 outputs.
    if (tid < 164) {
        const int t = tid;
        const float* srcbase;
        int srcstride, srcoff;
        if (t < 8) {
            srcbase = w1; srcstride = 8; srcoff = t;
        } else {
            int tt = t - 8;
            int p2 = 0, p3 = 0, rem = 0;
            bool found = false;
            for (int i = 0; i < 8 && !found; i++) {
                for (int j = i; j < 8; j++) {
                    const int blk = 1 + (8 - j);
                    if (tt < blk) { rem = tt; found = true; break; }
                    tt -= blk; p2++; p3 += 8 - j;
                }
            }
            if (rem == 0) { srcbase = w2; srcstride = 36;  srcoff = p2; }
            else          { srcbase = w3; srcstride = 120; srcoff = p3 + rem - 1; }
        }
#pragma unroll
        for (int o = 0; o < 8; o++) {
            const float v = srcbase[(g * 8 + o) * srcstride + srcoff];
            const unsigned int u = __float_as_uint(v);
            wdup[t * 8 + o] = ((u64)u << 32) | u;
        }
    }
    if (tid >= 192 && tid < 200) {
        const int o = tid - 192;
        const float v = b1[g * 8 + o] + b2[g * 8 + o] + b3[g * 8 + o];
        const unsigned int u = __float_as_uint(v);
        biasdup[o] = ((u64)u << 32) | u;
    }
    __syncthreads();

    // Pixel pair p in batches z and z+8.
    const int p = (blockIdx.x * TPB + tid) * 2;
    const size_t gbase = ((size_t)blockIdx.z * 256 + (size_t)g * 8) * HW + p;
    const size_t bstr  = (size_t)8 * 256 * HW;

    u64 XA[8], XB[8], accA[8], accB[8];
#pragma unroll
    for (int k = 0; k < 8; k++) {
        XA[k] = *(const u64*)(x + gbase + (size_t)k * HW);
        XB[k] = *(const u64*)(x + gbase + bstr + (size_t)k * HW);
    }
#pragma unroll
    for (int o = 0; o < 8; o++) { accA[o] = biasdup[o]; accB[o] = accA[o]; }

    ulonglong2 wE_0, wE_1, wE_2, wE_3;   // even-parity features
    ulonglong2 wO_0, wO_1, wO_2, wO_3;   // odd-parity features
    PREF(wE, 0);

    // Degree 1: traversal t = k.
#pragma unroll
    for (int k = 0; k < 8; k++)
        STEP(k, XA[k], XB[k]);

    // Pairs + triples; indices are closed-form in (i,j,k).
#pragma unroll
    for (int i = 0; i < 8; i++) {
#pragma unroll
        for (int j = i; j < 8; j++) {
            const u64 pA = mul2(XA[i], XA[j]);
            const u64 pB = mul2(XB[i], XB[j]);
            STEP(fcPair(i, j), pA, pB);
#pragma unroll
            for (int k = j; k < 8; k++)
                STEP(fcTrip(i, j, k), mul2(pA, XA[k]), mul2(pB, XB[k]));
        }
    }

#pragma unroll
    for (int o = 0; o < 8; o++) {
        *(u64*)(out + gbase + (size_t)o * HW) = accA[o];
        *(u64*)(out + gbase + bstr + (size_t)o * HW) = accB[o];
    }
}

extern "C" void kernel_launch(void* const* d_in, const int* in_sizes, int n_in,
                              void* d_out, int out_size)
{
    const float* x  = (const float*)d_in[0];
    const float* w1 = (const float*)d_in[1];
    const float* b1 = (const float*)d_in[2];
    const float* w2 = (const float*)d_in[3];
    const float* b2 = (const float*)d_in[4];
    const float* w3 = (const float*)d_in[5];
    const float* b3 = (const float*)d_in[6];

    dim3 grid(7, 32, 8);    // pixel-pair chunks, groups, batch pairs
    dim3 block(TPB);
    hoaf_kernel<<<grid, block>>>(x, w1, b1, w2, b2, w3, b3, (float*)d_out);
}